// round 15
// baseline (speedup 1.0000x reference)
#include <cuda_runtime.h>

// Problem dims
#define T_DIM 2048
#define B_DIM 16
#define D_DIM 1024
#define N_DIM 64
#define C_DIM 256   // 4*N

#define NUM_GEMM_CTAS 232
#define NUM_SCAN_CTAS 64           // 512 warps, 2 rows per warp
#define NUM_MTILES    256          // (T*B)/128 m-tiles; each = 8 timesteps
#define NUM_TILES     512          // 256 m-tiles x 2 n-tiles
#define STEPS_PER_CHUNK 8

// 32 MB scratch for projected k/v/q/m: (T, B, 4N)
__device__ float g_kvqm[(size_t)T_DIM * B_DIM * C_DIM];
// Per-m-tile completion counters (2 = both n-tiles done)
__device__ int g_done[NUM_MTILES];

__global__ void e80_zero_flags() {
    g_done[threadIdx.x] = 0;
}

// ---------------------------------------------------------------------------
// GEMM tile body: one 128x128 tile of kvqm = X * W^T (NT, fp32).
// ---------------------------------------------------------------------------
__device__ __forceinline__ void gemm_tile(const float* __restrict__ A,
                                          const float* __restrict__ W,
                                          int mBase, int nBase,
                                          float (*As)[128], float (*Bs)[128]) {
    const int K  = D_DIM;
    const int tid = threadIdx.x;
    const int lr = tid >> 2;          // 0..63 (and +64)
    const int kq = (tid & 3) * 4;     // 0,4,8,12

    const float* Ag = A + (size_t)(mBase + lr) * K + kq;
    const float* Wg = W + (size_t)(nBase + lr) * K + kq;

    float4 pa0 = *(const float4*)(Ag);
    float4 pa1 = *(const float4*)(Ag + (size_t)64 * K);
    float4 pb0 = *(const float4*)(Wg);
    float4 pb1 = *(const float4*)(Wg + (size_t)64 * K);

    const int tx = tid & 15;
    const int ty = tid >> 4;

    float acc[8][8];
#pragma unroll
    for (int i = 0; i < 8; i++)
#pragma unroll
        for (int j = 0; j < 8; j++) acc[i][j] = 0.0f;

    for (int k0 = 0; k0 < K; k0 += 16) {
        As[kq + 0][lr] = pa0.x; As[kq + 1][lr] = pa0.y;
        As[kq + 2][lr] = pa0.z; As[kq + 3][lr] = pa0.w;
        As[kq + 0][lr + 64] = pa1.x; As[kq + 1][lr + 64] = pa1.y;
        As[kq + 2][lr + 64] = pa1.z; As[kq + 3][lr + 64] = pa1.w;
        Bs[kq + 0][lr] = pb0.x; Bs[kq + 1][lr] = pb0.y;
        Bs[kq + 2][lr] = pb0.z; Bs[kq + 3][lr] = pb0.w;
        Bs[kq + 0][lr + 64] = pb1.x; Bs[kq + 1][lr + 64] = pb1.y;
        Bs[kq + 2][lr + 64] = pb1.z; Bs[kq + 3][lr + 64] = pb1.w;
        __syncthreads();

        if (k0 + 16 < K) {
            pa0 = *(const float4*)(Ag + k0 + 16);
            pa1 = *(const float4*)(Ag + (size_t)64 * K + k0 + 16);
            pb0 = *(const float4*)(Wg + k0 + 16);
            pb1 = *(const float4*)(Wg + (size_t)64 * K + k0 + 16);
        }

#pragma unroll
        for (int k = 0; k < 16; k++) {
            float ar[8], br[8];
            *(float4*)&ar[0] = *(const float4*)&As[k][ty * 8];
            *(float4*)&ar[4] = *(const float4*)&As[k][ty * 8 + 4];
            *(float4*)&br[0] = *(const float4*)&Bs[k][tx * 8];
            *(float4*)&br[4] = *(const float4*)&Bs[k][tx * 8 + 4];
#pragma unroll
            for (int i = 0; i < 8; i++)
#pragma unroll
                for (int j = 0; j < 8; j++)
                    acc[i][j] = fmaf(ar[i], br[j], acc[i][j]);
        }
        __syncthreads();
    }

#pragma unroll
    for (int i = 0; i < 8; i++) {
        float* Cp = g_kvqm + (size_t)(mBase + ty * 8 + i) * C_DIM + nBase + tx * 8;
        *(float4*)Cp       = make_float4(acc[i][0], acc[i][1], acc[i][2], acc[i][3]);
        *(float4*)(Cp + 4) = make_float4(acc[i][4], acc[i][5], acc[i][6], acc[i][7]);
    }
}

__device__ __forceinline__ float warp_sum(float p) {
#pragma unroll
    for (int off = 16; off > 0; off >>= 1)
        p += __shfl_xor_sync(0xffffffffu, p, off);
    return p;
}

// Consumer-side chunk wait (chunk m ready when both n-tiles committed).
__device__ __forceinline__ void wait_chunk(int m) {
    if (*(volatile int*)&g_done[m] < 2) {
        while (*(volatile int*)&g_done[m] < 2) __nanosleep(64);
    }
    __threadfence();   // acquire: order subsequent kvqm loads after flag
}

// Sigmoid-gated EMA update for a float2 of state, using the paired-RCP trick
// (one MUFU.RCP serves both sigmoids).
__device__ __forceinline__ void gate_update(float2& st, float a0, float a1,
                                            float2 bias) {
    float x0 = fmaxf(a0 + bias.x, -30.0f);
    float x1 = fmaxf(a1 + bias.y, -30.0f);
    float e0 = __expf(-x0), e1 = __expf(-x1);
    float d0 = 1.0f + e0,   d1 = 1.0f + e1;
    float r  = __fdividef(1.0f, d0 * d1);
    float g0 = r * d1,      g1 = r * d0;
    st.x = fmaf(g0, st.x - a0, a0);
    st.y = fmaf(g1, st.y - a1, a1);
}

// ---------------------------------------------------------------------------
// Fused kernel. Producer CTAs stream kvqm tiles in time order; consumer CTAs
// run the gated scan with TWO independent rows per warp (same batch, shared
// k/q/m loads) so the reduce/gate dependency chains of the two recurrences
// interleave and hide each other's latency.
// ---------------------------------------------------------------------------
__global__ __launch_bounds__(256, 2)
void e80_fused(const float* __restrict__ x,
               const float* __restrict__ S0,
               const float* __restrict__ M0,
               const float* __restrict__ W,
               const float* __restrict__ B_S,
               const float* __restrict__ B_M,
               float* __restrict__ out, int out_size) {
    __shared__ float As[16][128];
    __shared__ float Bs[16][128];

    if (blockIdx.x < NUM_GEMM_CTAS) {
        // ---------------- producer: persistent GEMM ----------------
        for (int L = blockIdx.x; L < NUM_TILES; L += NUM_GEMM_CTAS) {
            const int m = L >> 1;          // time-major tile order
            const int n = L & 1;
            gemm_tile(x, W, m * 128, n * 128, As, Bs);
            __threadfence();
            __syncthreads();
            if (threadIdx.x == 0) atomicAdd(&g_done[m], 1);
            __syncthreads();
        }
        return;
    }

    // ---------------- consumer: gated two-level scan, 2 rows/warp ----------
    const int warp = threadIdx.x >> 5;
    const int lane = threadIdx.x & 31;
    const int w    = (blockIdx.x - NUM_GEMM_CTAS) * 8 + warp;   // 0..511
    const int r0   = w * 2;            // rows r0, r0+1 (same batch)
    const int b    = r0 >> 6;
    const int i0   = r0 & 63;          // even

    // Per-lane persistent state for both rows.
    float2 bsA = ((const float2*)(B_S + i0 * N_DIM))[lane];
    float2 bsB = ((const float2*)(B_S + (i0 + 1) * N_DIM))[lane];
    float2 bmA = ((const float2*)(B_M + i0 * N_DIM))[lane];
    float2 bmB = ((const float2*)(B_M + (i0 + 1) * N_DIM))[lane];
    float2 sA  = ((const float2*)(S0 + (size_t)r0 * N_DIM))[lane];
    float2 sB  = ((const float2*)(S0 + (size_t)(r0 + 1) * N_DIM))[lane];
    float2 msA = ((const float2*)(M0 + (size_t)r0 * N_DIM))[lane];
    float2 msB = ((const float2*)(M0 + (size_t)(r0 + 1) * N_DIM))[lane];

    const float* basep = g_kvqm + b * C_DIM;
    float* outp = out + b * N_DIM + i0;        // lane-0 float2 store base

    for (int c = 0; c < NUM_MTILES; c++) {
        wait_chunk(c);

        // ---- batched loads for the whole 8-step chunk (high MLP) ----
        // k/q/m are shared by both rows; v comes as an aligned float2.
        float2 kk[STEPS_PER_CHUNK], qq[STEPS_PER_CHUNK], mm[STEPS_PER_CHUNK];
        float2 vv[STEPS_PER_CHUNK];
        const float* pc = basep + (size_t)c * STEPS_PER_CHUNK * (B_DIM * C_DIM);
#pragma unroll
        for (int u = 0; u < STEPS_PER_CHUNK; u++) {
            const float* p = pc + (size_t)u * (B_DIM * C_DIM);
            kk[u] = ((const float2*)(p      ))[lane];
            qq[u] = ((const float2*)(p + 128))[lane];
            mm[u] = ((const float2*)(p + 192))[lane];
            vv[u] = *(const float2*)(p + 64 + i0);
        }

        // ---- branch-free unrolled 8-step compute, 2 independent rows ----
#pragma unroll
        for (int u = 0; u < STEPS_PER_CHUNK; u++) {
            const float2 k2 = kk[u], q2 = qq[u], m2 = mm[u], v2 = vv[u];

            // S gates (rows A and B interleave — independent chains)
            gate_update(sA, v2.x * k2.x, v2.x * k2.y, bsA);
            gate_update(sB, v2.y * k2.x, v2.y * k2.y, bsB);

            // Sq = S @ q  (two independent warp allreduces)
            float SqA = warp_sum(fmaf(sA.x, q2.x, sA.y * q2.y));
            float SqB = warp_sum(fmaf(sB.x, q2.x, sB.y * q2.y));

            // M gates
            gate_update(msA, SqA * m2.x, SqA * m2.y, bmA);
            gate_update(msB, SqB * m2.x, SqB * m2.y, bmB);

            // out = M @ q
            float oA = warp_sum(fmaf(msA.x, q2.x, msA.y * q2.y));
            float oB = warp_sum(fmaf(msB.x, q2.x, msB.y * q2.y));
            if (lane == 0) {
                *(float2*)(outp + (size_t)(c * STEPS_PER_CHUNK + u) *
                                   (B_DIM * N_DIM)) = make_float2(oA, oB);
            }
        }
    }

    // Final states S_f, M_f packed after outs
    const int OUTS = T_DIM * B_DIM * N_DIM;
    const int STN  = B_DIM * N_DIM * N_DIM;
    if (out_size >= OUTS + 2 * STN) {
        ((float2*)(out + OUTS + (size_t)r0 * N_DIM))[lane]             = sA;
        ((float2*)(out + OUTS + (size_t)(r0 + 1) * N_DIM))[lane]       = sB;
        ((float2*)(out + OUTS + STN + (size_t)r0 * N_DIM))[lane]       = msA;
        ((float2*)(out + OUTS + STN + (size_t)(r0 + 1) * N_DIM))[lane] = msB;
    }
}

// ---------------------------------------------------------------------------
// Launch
// ---------------------------------------------------------------------------
extern "C" void kernel_launch(void* const* d_in, const int* in_sizes, int n_in,
                              void* d_out, int out_size) {
    const float* x   = (const float*)d_in[0];   // (T, B, D)
    const float* S0  = (const float*)d_in[1];   // (B, N, N)
    const float* M0  = (const float*)d_in[2];   // (B, N, N)
    const float* W   = (const float*)d_in[3];   // (4N, D)
    const float* B_S = (const float*)d_in[4];   // (N, N)
    const float* B_M = (const float*)d_in[5];   // (N, N)
    float* out = (float*)d_out;

    e80_zero_flags<<<1, NUM_MTILES>>>();
    e80_fused<<<NUM_GEMM_CTAS + NUM_SCAN_CTAS, 256>>>(
        x, S0, M0, W, B_S, B_M, out, out_size);
}

// round 16
// speedup vs baseline: 1.0009x; 1.0009x over previous
#include <cuda_runtime.h>

// Problem dims
#define T_DIM 2048
#define B_DIM 16
#define D_DIM 1024
#define N_DIM 64
#define C_DIM 256   // 4*N

#define NUM_GEMM_CTAS 232
#define NUM_SCAN_CTAS 64           // 512 warps, 2 rows per warp
#define NUM_MTILES    256          // (T*B)/128 m-tiles; each = 8 timesteps
#define NUM_TILES     512          // 256 m-tiles x 2 n-tiles
#define STEPS_PER_CHUNK 8

// 32 MB scratch for projected k/v/q/m: (T, B, 4N)
__device__ float g_kvqm[(size_t)T_DIM * B_DIM * C_DIM];
// Per-m-tile completion counters (2 = both n-tiles done)
__device__ int g_done[NUM_MTILES];

__global__ void e80_zero_flags() {
    g_done[threadIdx.x] = 0;
}

// ---------------------------------------------------------------------------
// GEMM tile body: one 128x128 tile of kvqm = X * W^T (NT, fp32).
// ---------------------------------------------------------------------------
__device__ __forceinline__ void gemm_tile(const float* __restrict__ A,
                                          const float* __restrict__ W,
                                          int mBase, int nBase,
                                          float (*As)[128], float (*Bs)[128]) {
    const int K  = D_DIM;
    const int tid = threadIdx.x;
    const int lr = tid >> 2;          // 0..63 (and +64)
    const int kq = (tid & 3) * 4;     // 0,4,8,12

    const float* Ag = A + (size_t)(mBase + lr) * K + kq;
    const float* Wg = W + (size_t)(nBase + lr) * K + kq;

    float4 pa0 = *(const float4*)(Ag);
    float4 pa1 = *(const float4*)(Ag + (size_t)64 * K);
    float4 pb0 = *(const float4*)(Wg);
    float4 pb1 = *(const float4*)(Wg + (size_t)64 * K);

    const int tx = tid & 15;
    const int ty = tid >> 4;

    float acc[8][8];
#pragma unroll
    for (int i = 0; i < 8; i++)
#pragma unroll
        for (int j = 0; j < 8; j++) acc[i][j] = 0.0f;

    for (int k0 = 0; k0 < K; k0 += 16) {
        As[kq + 0][lr] = pa0.x; As[kq + 1][lr] = pa0.y;
        As[kq + 2][lr] = pa0.z; As[kq + 3][lr] = pa0.w;
        As[kq + 0][lr + 64] = pa1.x; As[kq + 1][lr + 64] = pa1.y;
        As[kq + 2][lr + 64] = pa1.z; As[kq + 3][lr + 64] = pa1.w;
        Bs[kq + 0][lr] = pb0.x; Bs[kq + 1][lr] = pb0.y;
        Bs[kq + 2][lr] = pb0.z; Bs[kq + 3][lr] = pb0.w;
        Bs[kq + 0][lr + 64] = pb1.x; Bs[kq + 1][lr + 64] = pb1.y;
        Bs[kq + 2][lr + 64] = pb1.z; Bs[kq + 3][lr + 64] = pb1.w;
        __syncthreads();

        if (k0 + 16 < K) {
            pa0 = *(const float4*)(Ag + k0 + 16);
            pa1 = *(const float4*)(Ag + (size_t)64 * K + k0 + 16);
            pb0 = *(const float4*)(Wg + k0 + 16);
            pb1 = *(const float4*)(Wg + (size_t)64 * K + k0 + 16);
        }

#pragma unroll
        for (int k = 0; k < 16; k++) {
            float ar[8], br[8];
            *(float4*)&ar[0] = *(const float4*)&As[k][ty * 8];
            *(float4*)&ar[4] = *(const float4*)&As[k][ty * 8 + 4];
            *(float4*)&br[0] = *(const float4*)&Bs[k][tx * 8];
            *(float4*)&br[4] = *(const float4*)&Bs[k][tx * 8 + 4];
#pragma unroll
            for (int i = 0; i < 8; i++)
#pragma unroll
                for (int j = 0; j < 8; j++)
                    acc[i][j] = fmaf(ar[i], br[j], acc[i][j]);
        }
        __syncthreads();
    }

#pragma unroll
    for (int i = 0; i < 8; i++) {
        float* Cp = g_kvqm + (size_t)(mBase + ty * 8 + i) * C_DIM + nBase + tx * 8;
        *(float4*)Cp       = make_float4(acc[i][0], acc[i][1], acc[i][2], acc[i][3]);
        *(float4*)(Cp + 4) = make_float4(acc[i][4], acc[i][5], acc[i][6], acc[i][7]);
    }
}

__device__ __forceinline__ float warp_sum(float p) {
#pragma unroll
    for (int off = 16; off > 0; off >>= 1)
        p += __shfl_xor_sync(0xffffffffu, p, off);
    return p;
}

// Consumer-side chunk wait (chunk m ready when both n-tiles committed).
__device__ __forceinline__ void wait_chunk(int m) {
    if (*(volatile int*)&g_done[m] < 2) {
        while (*(volatile int*)&g_done[m] < 2) __nanosleep(64);
    }
    __threadfence();   // acquire: order subsequent kvqm loads after flag
}

// Sigmoid-gated EMA update for a float2 of state, using the paired-RCP trick
// (one MUFU.RCP serves both sigmoids).
__device__ __forceinline__ void gate_update(float2& st, float a0, float a1,
                                            float2 bias) {
    float x0 = fmaxf(a0 + bias.x, -30.0f);
    float x1 = fmaxf(a1 + bias.y, -30.0f);
    float e0 = __expf(-x0), e1 = __expf(-x1);
    float d0 = 1.0f + e0,   d1 = 1.0f + e1;
    float r  = __fdividef(1.0f, d0 * d1);
    float g0 = r * d1,      g1 = r * d0;
    st.x = fmaf(g0, st.x - a0, a0);
    st.y = fmaf(g1, st.y - a1, a1);
}

// ---------------------------------------------------------------------------
// Fused kernel. Producer CTAs stream kvqm tiles in time order; consumer CTAs
// run the gated scan with TWO independent rows per warp (same batch, shared
// k/q/m loads) so the reduce/gate dependency chains of the two recurrences
// interleave and hide each other's latency.
// ---------------------------------------------------------------------------
__global__ __launch_bounds__(256, 2)
void e80_fused(const float* __restrict__ x,
               const float* __restrict__ S0,
               const float* __restrict__ M0,
               const float* __restrict__ W,
               const float* __restrict__ B_S,
               const float* __restrict__ B_M,
               float* __restrict__ out, int out_size) {
    __shared__ float As[16][128];
    __shared__ float Bs[16][128];

    if (blockIdx.x < NUM_GEMM_CTAS) {
        // ---------------- producer: persistent GEMM ----------------
        for (int L = blockIdx.x; L < NUM_TILES; L += NUM_GEMM_CTAS) {
            const int m = L >> 1;          // time-major tile order
            const int n = L & 1;
            gemm_tile(x, W, m * 128, n * 128, As, Bs);
            __threadfence();
            __syncthreads();
            if (threadIdx.x == 0) atomicAdd(&g_done[m], 1);
            __syncthreads();
        }
        return;
    }

    // ---------------- consumer: gated two-level scan, 2 rows/warp ----------
    const int warp = threadIdx.x >> 5;
    const int lane = threadIdx.x & 31;
    const int w    = (blockIdx.x - NUM_GEMM_CTAS) * 8 + warp;   // 0..511
    const int r0   = w * 2;            // rows r0, r0+1 (same batch)
    const int b    = r0 >> 6;
    const int i0   = r0 & 63;          // even

    // Per-lane persistent state for both rows.
    float2 bsA = ((const float2*)(B_S + i0 * N_DIM))[lane];
    float2 bsB = ((const float2*)(B_S + (i0 + 1) * N_DIM))[lane];
    float2 bmA = ((const float2*)(B_M + i0 * N_DIM))[lane];
    float2 bmB = ((const float2*)(B_M + (i0 + 1) * N_DIM))[lane];
    float2 sA  = ((const float2*)(S0 + (size_t)r0 * N_DIM))[lane];
    float2 sB  = ((const float2*)(S0 + (size_t)(r0 + 1) * N_DIM))[lane];
    float2 msA = ((const float2*)(M0 + (size_t)r0 * N_DIM))[lane];
    float2 msB = ((const float2*)(M0 + (size_t)(r0 + 1) * N_DIM))[lane];

    const float* basep = g_kvqm + b * C_DIM;
    float* outp = out + b * N_DIM + i0;        // lane-0 float2 store base

    for (int c = 0; c < NUM_MTILES; c++) {
        wait_chunk(c);

        // ---- batched loads for the whole 8-step chunk (high MLP) ----
        // k/q/m are shared by both rows; v comes as an aligned float2.
        float2 kk[STEPS_PER_CHUNK], qq[STEPS_PER_CHUNK], mm[STEPS_PER_CHUNK];
        float2 vv[STEPS_PER_CHUNK];
        const float* pc = basep + (size_t)c * STEPS_PER_CHUNK * (B_DIM * C_DIM);
#pragma unroll
        for (int u = 0; u < STEPS_PER_CHUNK; u++) {
            const float* p = pc + (size_t)u * (B_DIM * C_DIM);
            kk[u] = ((const float2*)(p      ))[lane];
            qq[u] = ((const float2*)(p + 128))[lane];
            mm[u] = ((const float2*)(p + 192))[lane];
            vv[u] = *(const float2*)(p + 64 + i0);
        }

        // ---- branch-free unrolled 8-step compute, 2 independent rows ----
#pragma unroll
        for (int u = 0; u < STEPS_PER_CHUNK; u++) {
            const float2 k2 = kk[u], q2 = qq[u], m2 = mm[u], v2 = vv[u];

            // S gates (rows A and B interleave — independent chains)
            gate_update(sA, v2.x * k2.x, v2.x * k2.y, bsA);
            gate_update(sB, v2.y * k2.x, v2.y * k2.y, bsB);

            // Sq = S @ q  (two independent warp allreduces)
            float SqA = warp_sum(fmaf(sA.x, q2.x, sA.y * q2.y));
            float SqB = warp_sum(fmaf(sB.x, q2.x, sB.y * q2.y));

            // M gates
            gate_update(msA, SqA * m2.x, SqA * m2.y, bmA);
            gate_update(msB, SqB * m2.x, SqB * m2.y, bmB);

            // out = M @ q
            float oA = warp_sum(fmaf(msA.x, q2.x, msA.y * q2.y));
            float oB = warp_sum(fmaf(msB.x, q2.x, msB.y * q2.y));
            if (lane == 0) {
                *(float2*)(outp + (size_t)(c * STEPS_PER_CHUNK + u) *
                                   (B_DIM * N_DIM)) = make_float2(oA, oB);
            }
        }
    }

    // Final states S_f, M_f packed after outs
    const int OUTS = T_DIM * B_DIM * N_DIM;
    const int STN  = B_DIM * N_DIM * N_DIM;
    if (out_size >= OUTS + 2 * STN) {
        ((float2*)(out + OUTS + (size_t)r0 * N_DIM))[lane]             = sA;
        ((float2*)(out + OUTS + (size_t)(r0 + 1) * N_DIM))[lane]       = sB;
        ((float2*)(out + OUTS + STN + (size_t)r0 * N_DIM))[lane]       = msA;
        ((float2*)(out + OUTS + STN + (size_t)(r0 + 1) * N_DIM))[lane] = msB;
    }
}

// ---------------------------------------------------------------------------
// Launch
// ---------------------------------------------------------------------------
extern "C" void kernel_launch(void* const* d_in, const int* in_sizes, int n_in,
                              void* d_out, int out_size) {
    const float* x   = (const float*)d_in[0];   // (T, B, D)
    const float* S0  = (const float*)d_in[1];   // (B, N, N)
    const float* M0  = (const float*)d_in[2];   // (B, N, N)
    const float* W   = (const float*)d_in[3];   // (4N, D)
    const float* B_S = (const float*)d_in[4];   // (N, N)
    const float* B_M = (const float*)d_in[5];   // (N, N)
    float* out = (float*)d_out;

    e80_zero_flags<<<1, NUM_MTILES>>>();
    e80_fused<<<NUM_GEMM_CTAS + NUM_SCAN_CTAS, 256>>>(
        x, S0, M0, W, B_S, B_M, out, out_size);
}

// round 17
// speedup vs baseline: 1.2834x; 1.2822x over previous
#include <cuda_runtime.h>

// Problem dims
#define T_DIM 2048
#define B_DIM 16
#define D_DIM 1024
#define N_DIM 64
#define C_DIM 256   // 4*N

#define NUM_GEMM_CTAS 168
#define NUM_SCAN_CTAS 128          // 1024 warps, 1 row per warp
#define NUM_MTILES    256          // (T*B)/128 m-tiles; each = 8 timesteps
#define NUM_TILES     512          // 256 m-tiles x 2 n-tiles
#define SPC 8                      // steps per chunk

// 32 MB scratch for projected k/v/q/m: (T, B, 4N)
__device__ float g_kvqm[(size_t)T_DIM * B_DIM * C_DIM];
// Per-m-tile completion counters (2 = both n-tiles done)
__device__ int g_done[NUM_MTILES];

__global__ void e80_zero_flags() {
    g_done[threadIdx.x] = 0;
}

// ---------------------------------------------------------------------------
// GEMM tile body: one 128x128 tile of kvqm = X * W^T (NT, fp32).
// ---------------------------------------------------------------------------
__device__ __forceinline__ void gemm_tile(const float* __restrict__ A,
                                          const float* __restrict__ W,
                                          int mBase, int nBase,
                                          float (*As)[128], float (*Bs)[128]) {
    const int K  = D_DIM;
    const int tid = threadIdx.x;
    const int lr = tid >> 2;          // 0..63 (and +64)
    const int kq = (tid & 3) * 4;     // 0,4,8,12

    const float* Ag = A + (size_t)(mBase + lr) * K + kq;
    const float* Wg = W + (size_t)(nBase + lr) * K + kq;

    float4 pa0 = *(const float4*)(Ag);
    float4 pa1 = *(const float4*)(Ag + (size_t)64 * K);
    float4 pb0 = *(const float4*)(Wg);
    float4 pb1 = *(const float4*)(Wg + (size_t)64 * K);

    const int tx = tid & 15;
    const int ty = tid >> 4;

    float acc[8][8];
#pragma unroll
    for (int i = 0; i < 8; i++)
#pragma unroll
        for (int j = 0; j < 8; j++) acc[i][j] = 0.0f;

    for (int k0 = 0; k0 < K; k0 += 16) {
        As[kq + 0][lr] = pa0.x; As[kq + 1][lr] = pa0.y;
        As[kq + 2][lr] = pa0.z; As[kq + 3][lr] = pa0.w;
        As[kq + 0][lr + 64] = pa1.x; As[kq + 1][lr + 64] = pa1.y;
        As[kq + 2][lr + 64] = pa1.z; As[kq + 3][lr + 64] = pa1.w;
        Bs[kq + 0][lr] = pb0.x; Bs[kq + 1][lr] = pb0.y;
        Bs[kq + 2][lr] = pb0.z; Bs[kq + 3][lr] = pb0.w;
        Bs[kq + 0][lr + 64] = pb1.x; Bs[kq + 1][lr + 64] = pb1.y;
        Bs[kq + 2][lr + 64] = pb1.z; Bs[kq + 3][lr + 64] = pb1.w;
        __syncthreads();

        if (k0 + 16 < K) {
            pa0 = *(const float4*)(Ag + k0 + 16);
            pa1 = *(const float4*)(Ag + (size_t)64 * K + k0 + 16);
            pb0 = *(const float4*)(Wg + k0 + 16);
            pb1 = *(const float4*)(Wg + (size_t)64 * K + k0 + 16);
        }

#pragma unroll
        for (int k = 0; k < 16; k++) {
            float ar[8], br[8];
            *(float4*)&ar[0] = *(const float4*)&As[k][ty * 8];
            *(float4*)&ar[4] = *(const float4*)&As[k][ty * 8 + 4];
            *(float4*)&br[0] = *(const float4*)&Bs[k][tx * 8];
            *(float4*)&br[4] = *(const float4*)&Bs[k][tx * 8 + 4];
#pragma unroll
            for (int i = 0; i < 8; i++)
#pragma unroll
                for (int j = 0; j < 8; j++)
                    acc[i][j] = fmaf(ar[i], br[j], acc[i][j]);
        }
        __syncthreads();
    }

#pragma unroll
    for (int i = 0; i < 8; i++) {
        float* Cp = g_kvqm + (size_t)(mBase + ty * 8 + i) * C_DIM + nBase + tx * 8;
        *(float4*)Cp       = make_float4(acc[i][0], acc[i][1], acc[i][2], acc[i][3]);
        *(float4*)(Cp + 4) = make_float4(acc[i][4], acc[i][5], acc[i][6], acc[i][7]);
    }
}

// Consumer-side chunk wait (chunk m ready when both n-tiles committed).
__device__ __forceinline__ void wait_chunk(int m) {
    if (*(volatile int*)&g_done[m] < 2) {
        while (*(volatile int*)&g_done[m] < 2) __nanosleep(64);
    }
    __threadfence();   // acquire: order subsequent kvqm loads after flag
}

// Paired sigmoid gates: one RCP serves both (clamped to avoid inf*0 NaN).
__device__ __forceinline__ void sig2(float a0, float a1, float2 bias,
                                     float& g0, float& g1) {
    float x0 = fmaxf(a0 + bias.x, -30.0f);
    float x1 = fmaxf(a1 + bias.y, -30.0f);
    float e0 = __expf(-x0), e1 = __expf(-x1);
    float d0 = 1.0f + e0,   d1 = 1.0f + e1;
    float r  = __fdividef(1.0f, d0 * d1);
    g0 = r * d1;
    g1 = r * d0;
}

// ---------------------------------------------------------------------------
// Fused kernel. Producers stream kvqm tiles time-major; consumers run the
// gated scan with the 8-step chunk PHASE-SPLIT: gates precomputed (indep),
// short carried FMA chains, and the 8 warp-reduces batched level-by-level so
// SHFL latency is paid once per level instead of once per step.
// ---------------------------------------------------------------------------
__global__ __launch_bounds__(256, 2)
void e80_fused(const float* __restrict__ x,
               const float* __restrict__ S0,
               const float* __restrict__ M0,
               const float* __restrict__ W,
               const float* __restrict__ B_S,
               const float* __restrict__ B_M,
               float* __restrict__ out, int out_size) {
    __shared__ float As[16][128];
    __shared__ float Bs[16][128];

    if (blockIdx.x < NUM_GEMM_CTAS) {
        // ---------------- producer: persistent GEMM ----------------
        for (int L = blockIdx.x; L < NUM_TILES; L += NUM_GEMM_CTAS) {
            const int m = L >> 1;          // time-major tile order
            const int n = L & 1;
            gemm_tile(x, W, m * 128, n * 128, As, Bs);
            __threadfence();
            __syncthreads();
            if (threadIdx.x == 0) atomicAdd(&g_done[m], 1);
            __syncthreads();
        }
        return;
    }

    // ---------------- consumer: gated two-level scan ----------------
    const int warp = threadIdx.x >> 5;
    const int lane = threadIdx.x & 31;
    const int row  = (blockIdx.x - NUM_GEMM_CTAS) * 8 + warp;   // 0..1023
    const int b    = row >> 6;
    const int i    = row & 63;

    float2 bs2 = ((const float2*)(B_S + i * N_DIM))[lane];
    float2 bm2 = ((const float2*)(B_M + i * N_DIM))[lane];
    float2 s   = ((const float2*)(S0 + (size_t)row * N_DIM))[lane];
    float2 ms  = ((const float2*)(M0 + (size_t)row * N_DIM))[lane];

    const float* basep = g_kvqm + b * C_DIM;
    float* outp = out + b * N_DIM + i;

    for (int c = 0; c < NUM_MTILES; c++) {
        wait_chunk(c);

        // ---- Phase 0: loads + S-gate precompute (all independent) ----
        float2 qq[SPC], mm[SPC];
        float vk0[SPC], vk1[SPC], g0[SPC], g1[SPC];
        const float* pc = basep + (size_t)c * SPC * (B_DIM * C_DIM);
#pragma unroll
        for (int u = 0; u < SPC; u++) {
            const float* p = pc + (size_t)u * (B_DIM * C_DIM);
            float2 k2 = ((const float2*)(p      ))[lane];
            qq[u]     = ((const float2*)(p + 128))[lane];
            mm[u]     = ((const float2*)(p + 192))[lane];
            float v   = p[64 + i];
            vk0[u] = v * k2.x;
            vk1[u] = v * k2.y;
            sig2(vk0[u], vk1[u], bs2, g0[u], g1[u]);   // gate indep of S
        }

        // ---- Phase 1: S carried chain (2 FMAs/step) + first partials ----
        float p1[SPC];
#pragma unroll
        for (int u = 0; u < SPC; u++) {
            s.x = fmaf(g0[u], s.x - vk0[u], vk0[u]);
            s.y = fmaf(g1[u], s.y - vk1[u], vk1[u]);
            p1[u] = fmaf(s.x, qq[u].x, s.y * qq[u].y);
        }

        // ---- Phase 2: 8 reduces batched per level (SHFLs independent) ----
#pragma unroll
        for (int off = 16; off > 0; off >>= 1) {
#pragma unroll
            for (int u = 0; u < SPC; u++)
                p1[u] += __shfl_xor_sync(0xffffffffu, p1[u], off);
        }

        // ---- Phase 3: M gates (indep across u) + ms chain + out partials --
        float op[SPC];
#pragma unroll
        for (int u = 0; u < SPC; u++) {
            float sm0 = p1[u] * mm[u].x;
            float sm1 = p1[u] * mm[u].y;
            float h0, h1;
            sig2(sm0, sm1, bm2, h0, h1);               // gate indep of M
            ms.x = fmaf(h0, ms.x - sm0, sm0);
            ms.y = fmaf(h1, ms.y - sm1, sm1);
            op[u] = fmaf(ms.x, qq[u].x, ms.y * qq[u].y);
        }

        // ---- Phase 4: 8 output reduces batched per level + stores ----
#pragma unroll
        for (int off = 16; off > 0; off >>= 1) {
#pragma unroll
            for (int u = 0; u < SPC; u++)
                op[u] += __shfl_xor_sync(0xffffffffu, op[u], off);
        }
        if (lane == 0) {
#pragma unroll
            for (int u = 0; u < SPC; u++)
                outp[(size_t)(c * SPC + u) * (B_DIM * N_DIM)] = op[u];
        }
    }

    // Final states S_f, M_f packed after outs
    const int OUTS = T_DIM * B_DIM * N_DIM;
    const int STN  = B_DIM * N_DIM * N_DIM;
    if (out_size >= OUTS + 2 * STN) {
        ((float2*)(out + OUTS + (size_t)row * N_DIM))[lane]       = s;
        ((float2*)(out + OUTS + STN + (size_t)row * N_DIM))[lane] = ms;
    }
}

// ---------------------------------------------------------------------------
// Launch
// ---------------------------------------------------------------------------
extern "C" void kernel_launch(void* const* d_in, const int* in_sizes, int n_in,
                              void* d_out, int out_size) {
    const float* x   = (const float*)d_in[0];   // (T, B, D)
    const float* S0  = (const float*)d_in[1];   // (B, N, N)
    const float* M0  = (const float*)d_in[2];   // (B, N, N)
    const float* W   = (const float*)d_in[3];   // (4N, D)
    const float* B_S = (const float*)d_in[4];   // (N, N)
    const float* B_M = (const float*)d_in[5];   // (N, N)
    float* out = (float*)d_out;

    e80_zero_flags<<<1, NUM_MTILES>>>();
    e80_fused<<<NUM_GEMM_CTAS + NUM_SCAN_CTAS, 256>>>(
        x, S0, M0, W, B_S, B_M, out, out_size);
}